// round 4
// baseline (speedup 1.0000x reference)
#include <cuda_runtime.h>
#include <math.h>

// Problem constants
#define BN 4
#define CN 64
#define HN 128
#define WN 128
#define ON 64
#define K2C 9
#define HW (HN*WN)
#define CK 576          // CN * K2C

typedef unsigned long long ull;

// ---------------- scratch (no allocs allowed) ----------------
__device__ __align__(16) float g_sy[BN*K2C*HW];   // sample y coords
__device__ __align__(16) float g_sx[BN*K2C*HW];   // sample x coords
__device__ __align__(16) float g_mm[BN*HW];       // mean sigmoid modulation
__device__ __align__(16) float g_wT[K2C*CN*ON];   // main weight as [k][c][o]

// ---------------- f32x2 helpers ----------------
__device__ __forceinline__ ull pack2(float lo, float hi){
  ull r; asm("mov.b64 %0, {%1,%2};" : "=l"(r) : "f"(lo), "f"(hi)); return r;
}
__device__ __forceinline__ void unpack2(ull v, float& lo, float& hi){
  asm("mov.b64 {%0,%1}, %2;" : "=f"(lo), "=f"(hi) : "l"(v));
}
__device__ __forceinline__ void ffma2(ull& d, ull a, ull b){
  asm("fma.rn.f32x2 %0, %1, %2, %0;" : "+l"(d) : "l"(a), "l"(b));
}

// ---------------- kernel A: offset + modulation conv ----------------
__device__ __forceinline__ void write_pix(int b, int ho, int wo,
                                          const float* __restrict__ offb,
                                          const float* __restrict__ modb,
                                          const float (&rr)[28]){
  float msum = 0.f;
  #pragma unroll
  for (int k = 0; k < 9; k++){
    float kyf = (float)(k/3) - 1.f;
    float kxf = (float)(k%3) - 1.f;
    int idx = ((b*9 + k)*HN + ho)*WN + wo;
    g_sy[idx] = (float)ho + kyf + rr[k]     + offb[k];
    g_sx[idx] = (float)wo + kxf + rr[9 + k] + offb[9 + k];
    float z = rr[18 + k] + modb[k];
    msum += 1.f / (1.f + expf(-z));
  }
  g_mm[(b*HN + ho)*WN + wo] = msum * (1.f/9.f);
}

#define OSM_BYTES (CK*28*4)   // 64512 B

__global__ __launch_bounds__(256, 3)
void offset_kernel(const float* __restrict__ x,
                   const float* __restrict__ offw,
                   const float* __restrict__ modw,
                   const float* __restrict__ offb,
                   const float* __restrict__ modb){
  extern __shared__ ull wsmA[];          // [CK][14] f32x2 pairs
  float* wf = (float*)wsmA;
  // transpose-fill: wf[ct*28 + ch]
  for (int i = threadIdx.x; i < 18*CK; i += 256){
    int ch = i / CK, ct = i % CK;
    wf[ct*28 + ch] = offw[i];
  }
  for (int i = threadIdx.x; i < 9*CK; i += 256){
    int ch = i / CK, ct = i % CK;
    wf[ct*28 + 18 + ch] = modw[i];
  }
  for (int i = threadIdx.x; i < CK; i += 256) wf[i*28 + 27] = 0.f;
  __syncthreads();

  const int b  = blockIdx.y;
  const int wo = threadIdx.x & 127;
  const int ho = blockIdx.x*2 + (threadIdx.x >> 7);   // 1 px per thread
  const float* xb = x + b*CN*HW;

  ull acc[14];
  #pragma unroll
  for (int j = 0; j < 14; j++) acc[j] = 0ull;

  const bool cok0 = (wo - 1) >= 0;
  const bool cok2 = (wo + 1) < WN;

  for (int c = 0; c < CN; ++c){
    const float* xc = xb + c*HW;
    float xv[3][3];
    #pragma unroll
    for (int r = 0; r < 3; r++){
      int row = ho - 1 + r;
      bool rok = (row >= 0) && (row < HN);
      const float* xr = xc + row*WN;
      xv[r][0] = (rok && cok0) ? xr[wo-1] : 0.f;
      xv[r][1] =  rok          ? xr[wo]   : 0.f;
      xv[r][2] = (rok && cok2) ? xr[wo+1] : 0.f;
    }
    #pragma unroll
    for (int ky = 0; ky < 3; ky++){
      #pragma unroll
      for (int kx = 0; kx < 3; kx++){
        const int tap = ky*3 + kx;
        ull a = pack2(xv[ky][kx], xv[ky][kx]);
        const ull* wp = wsmA + (c*9 + tap)*14;   // uniform addr -> broadcast LDS
        #pragma unroll
        for (int j = 0; j < 14; j++) ffma2(acc[j], wp[j], a);
      }
    }
  }

  float rr[28];
  #pragma unroll
  for (int j = 0; j < 14; j++) unpack2(acc[j], rr[2*j], rr[2*j+1]);
  write_pix(b, ho, wo, offb, modb, rr);
}

// ---------------- kernel B: main-weight transpose ----------------
__global__ void prep_weights(const float* __restrict__ weight){
  int i = blockIdx.x*blockDim.x + threadIdx.x;
  if (i < K2C*CN*ON){
    int o = i & 63, c = (i >> 6) & 63, k = i >> 12;
    g_wT[i] = weight[(o*CN + c)*K2C + k];
  }
}

// ---------------- kernel C: smem-tiled bilinear sample + implicit GEMM ----------------
// CTA = full row: 128 px x 64 o, 512 threads, 1 CTA/SM.
// x tile [64c][5 rows (ho-2..ho+2 clamped)][132 cols (-2..129 clamped)] in smem;
// sampling becomes 4 LDS per (c,px) with exact global-gather fallback for huge offsets.
#define XT_R 5
#define XT_C 132
#define XT_CH (XT_R*XT_C)                       // 660 floats per channel
#define DSM_BYTES (CN*XT_CH*4 + CN*WN*4 + CN*ON*4)   // 165KB + 32KB + 16KB = 218112

__global__ __launch_bounds__(512, 1)
void deform_kernel(const float* __restrict__ x,
                   const float* __restrict__ bias,
                   float* __restrict__ out){
  extern __shared__ char dsm[];
  float* xt  = (float*)dsm;                       // [c][5][132]
  float* ssm = (float*)(dsm + CN*XT_CH*4);        // [c][128]
  float* wsm = (float*)(dsm + CN*XT_CH*4 + CN*WN*4); // [c][64]

  const int b   = blockIdx.y;
  const int ho  = blockIdx.x;
  const int tid = threadIdx.x;
  const float* xb = x + b*CN*HW;

  // ---- stage x tile (once per CTA) ----
  for (int i = tid; i < CN*XT_CH; i += 512){
    int j = i % XT_C;
    int r = (i / XT_C) % XT_R;
    int c = i / XT_CH;
    int g  = min(max(ho - 2 + r, 0), HN-1);
    int gx = min(max(j - 2, 0), WN-1);
    xt[i] = xb[c*HW + g*WN + gx];
  }
  __syncthreads();

  // sampling mapping: 1 px x 16 channels per thread
  const int px = tid & 127;
  const int cg = tid >> 7;           // 0..3
  // gemm mapping: 8 o x 2 px per thread; lane = og*4 + pg_l for broadcast LDS
  const int lane  = tid & 31;
  const int warp  = tid >> 5;        // 0..15
  const int obase = (lane >> 2) * 8;             // 0..56
  const int pxb   = (warp*4 + (lane & 3)) * 2;   // 0..126 step 2

  ull acc[4][2];   // [o-pair][px]
  #pragma unroll
  for (int j = 0; j < 4; j++){ acc[j][0] = 0ull; acc[j][1] = 0ull; }

  for (int k = 0; k < 9; k++){
    if (k) __syncthreads();          // prev GEMM done before ssm/wsm overwrite

    // stage weight slice [c][o] for this tap
    {
      const float4* wsrc = (const float4*)(g_wT + k*CN*ON);
      float4* wdst = (float4*)wsm;
      #pragma unroll
      for (int i = 0; i < 2; i++) wdst[tid + i*512] = wsrc[tid + i*512];
    }

    // bilinear sample from smem tile (fallback: global gather)
    {
      const int sidx = ((b*9 + k)*HN + ho)*WN + px;
      float sy = g_sy[sidx], sx = g_sx[sidx];
      float y0f = floorf(sy), x0f = floorf(sx);
      float wy1 = sy - y0f, wx1 = sx - x0f;
      float wy0 = 1.f - wy1, wx0 = 1.f - wx1;
      int y0 = (int)y0f, x0i = (int)x0f;
      int y1 = y0 + 1,  x1i = x0i + 1;
      float my0 = (y0  >= 0 && y0  < HN) ? 1.f : 0.f;
      float my1 = (y1  >= 0 && y1  < HN) ? 1.f : 0.f;
      float mx0 = (x0i >= 0 && x0i < WN) ? 1.f : 0.f;
      float mx1 = (x1i >= 0 && x1i < WN) ? 1.f : 0.f;
      float w00 = wy0*wx0*my0*mx0, w01 = wy0*wx1*my0*mx1;
      float w10 = wy1*wx0*my1*mx0, w11 = wy1*wx1*my1*mx1;

      bool fast = (y0 >= ho-2) && (y1 <= ho+2) && (x0i >= -2) && (x1i <= WN+1);
      if (fast){
        int t00 = (y0 - (ho-2))*XT_C + (x0i + 2);
        int t01 = t00 + 1;
        int t10 = t00 + XT_C;
        int t11 = t10 + 1;
        const float* xc = xt + cg*16*XT_CH;
        #pragma unroll 4
        for (int i = 0; i < 16; i++){
          float v = w00*xc[t00] + w01*xc[t01] + w10*xc[t10] + w11*xc[t11];
          ssm[(cg*16 + i)*WN + px] = v;
          xc += XT_CH;
        }
      } else {
        int cy0 = min(max(y0, 0), HN-1),  cy1 = min(max(y1, 0), HN-1);
        int cx0 = min(max(x0i, 0), WN-1), cx1 = min(max(x1i, 0), WN-1);
        int i00 = cy0*WN + cx0, i01 = cy0*WN + cx1;
        int i10 = cy1*WN + cx0, i11 = cy1*WN + cx1;
        const float* xc = xb + cg*16*HW;
        #pragma unroll 4
        for (int i = 0; i < 16; i++){
          float v = w00*xc[i00] + w01*xc[i01] + w10*xc[i10] + w11*xc[i11];
          ssm[(cg*16 + i)*WN + px] = v;
          xc += HW;
        }
      }
    }
    __syncthreads();

    // GEMM: 8o x 2px per thread (3 LDS + 4 MOV + 8 FFMA2 per c)
    #pragma unroll 4
    for (int c = 0; c < CN; c++){
      const float* wrow = wsm + c*ON + obase;
      ulonglong2 wA = *(const ulonglong2*)(wrow);       // (w0,w1),(w2,w3)
      ulonglong2 wB = *(const ulonglong2*)(wrow + 4);   // (w4,w5),(w6,w7)
      float2 sv = *(const float2*)(ssm + c*WN + pxb);
      ull sd0 = pack2(sv.x, sv.x);
      ull sd1 = pack2(sv.y, sv.y);
      ffma2(acc[0][0], wA.x, sd0);
      ffma2(acc[0][1], wA.x, sd1);
      ffma2(acc[1][0], wA.y, sd0);
      ffma2(acc[1][1], wA.y, sd1);
      ffma2(acc[2][0], wB.x, sd0);
      ffma2(acc[2][1], wB.x, sd1);
      ffma2(acc[3][0], wB.y, sd0);
      ffma2(acc[3][1], wB.y, sd1);
    }
  }

  // epilogue: * mod_mean + bias
  float2 mmv = *(const float2*)&g_mm[(b*HN + ho)*WN + pxb];
  #pragma unroll
  for (int j = 0; j < 4; j++){
    float lo0, hi0, lo1, hi1;
    unpack2(acc[j][0], lo0, hi0);   // px0: o, o+1
    unpack2(acc[j][1], lo1, hi1);   // px1: o, o+1
    int o0 = obase + 2*j;
    float b0 = bias[o0], b1 = bias[o0 + 1];
    float2 r0 = make_float2(lo0*mmv.x + b0, lo1*mmv.y + b0);
    float2 r1 = make_float2(hi0*mmv.x + b1, hi1*mmv.y + b1);
    *(float2*)&out[((b*ON + o0    )*HN + ho)*WN + pxb] = r0;
    *(float2*)&out[((b*ON + o0 + 1)*HN + ho)*WN + pxb] = r1;
  }
}

// ---------------- launch ----------------
extern "C" void kernel_launch(void* const* d_in, const int* in_sizes, int n_in,
                              void* d_out, int out_size) {
  const float* x      = (const float*)d_in[0];
  const float* weight = (const float*)d_in[1];
  const float* bias   = (const float*)d_in[2];
  const float* offw   = (const float*)d_in[3];
  const float* offb   = (const float*)d_in[4];
  const float* modw   = (const float*)d_in[5];
  const float* modb   = (const float*)d_in[6];
  float* out = (float*)d_out;

  cudaFuncSetAttribute(offset_kernel, cudaFuncAttributeMaxDynamicSharedMemorySize, OSM_BYTES);
  cudaFuncSetAttribute(deform_kernel, cudaFuncAttributeMaxDynamicSharedMemorySize, DSM_BYTES);

  offset_kernel<<<dim3(64, BN), 256, OSM_BYTES>>>(x, offw, modw, offb, modb);
  prep_weights<<<144, 256>>>(weight);
  deform_kernel<<<dim3(HN, BN), 512, DSM_BYTES>>>(x, bias, out);
}

// round 7
// speedup vs baseline: 1.8787x; 1.8787x over previous
#include <cuda_runtime.h>
#include <cuda_fp16.h>
#include <math.h>
#include <stdint.h>

// Problem constants
#define BN 4
#define CN 64
#define HN 128
#define WN 128
#define ON 64
#define K2C 9
#define HW (HN*WN)
#define CK 576          // CN * K2C

typedef unsigned long long ull;

// ---------------- scratch ----------------
__device__ __align__(16) float  g_sy[BN*K2C*HW];   // sample y coords
__device__ __align__(16) float  g_sx[BN*K2C*HW];   // sample x coords
__device__ __align__(16) float  g_mm[BN*HW];       // mean sigmoid modulation
__device__ __align__(16) __half g_wh[K2C*ON*CN];   // main weight f16 as [tap][o][c]

// ---------------- f32x2 helpers (offset kernel) ----------------
__device__ __forceinline__ ull pack2(float lo, float hi){
  ull r; asm("mov.b64 %0, {%1,%2};" : "=l"(r) : "f"(lo), "f"(hi)); return r;
}
__device__ __forceinline__ void unpack2(ull v, float& lo, float& hi){
  asm("mov.b64 {%0,%1}, %2;" : "=f"(lo), "=f"(hi) : "l"(v));
}
__device__ __forceinline__ void ffma2(ull& d, ull a, ull b){
  asm("fma.rn.f32x2 %0, %1, %2, %0;" : "+l"(d) : "l"(a), "l"(b));
}

// ---------------- mma.sync m16n8k16 f16->f32 (base PTX, works on sm_103) ----------------
__device__ __forceinline__ void mma16816(float* d,
                                         uint32_t a0, uint32_t a1, uint32_t a2, uint32_t a3,
                                         uint32_t b0, uint32_t b1){
  asm volatile(
    "mma.sync.aligned.m16n8k16.row.col.f32.f16.f16.f32 "
    "{%0,%1,%2,%3}, {%4,%5,%6,%7}, {%8,%9}, {%0,%1,%2,%3};"
    : "+f"(d[0]), "+f"(d[1]), "+f"(d[2]), "+f"(d[3])
    : "r"(a0), "r"(a1), "r"(a2), "r"(a3), "r"(b0), "r"(b1));
}

// ---------------- kernel A: offset + modulation conv ----------------
__device__ __forceinline__ void write_pix(int b, int ho, int wo,
                                          const float* __restrict__ offb,
                                          const float* __restrict__ modb,
                                          const float (&rr)[28]){
  float msum = 0.f;
  #pragma unroll
  for (int k = 0; k < 9; k++){
    float kyf = (float)(k/3) - 1.f;
    float kxf = (float)(k%3) - 1.f;
    int idx = ((b*9 + k)*HN + ho)*WN + wo;
    g_sy[idx] = (float)ho + kyf + rr[k]     + offb[k];
    g_sx[idx] = (float)wo + kxf + rr[9 + k] + offb[9 + k];
    float z = rr[18 + k] + modb[k];
    msum += 1.f / (1.f + expf(-z));
  }
  g_mm[(b*HN + ho)*WN + wo] = msum * (1.f/9.f);
}

#define OSM_BYTES (CK*28*4)   // 64512 B

__global__ __launch_bounds__(256, 3)
void offset_kernel(const float* __restrict__ x,
                   const float* __restrict__ offw,
                   const float* __restrict__ modw,
                   const float* __restrict__ offb,
                   const float* __restrict__ modb){
  extern __shared__ ull wsmA[];          // [CK][14] f32x2 pairs (rows 112B, 16B aligned)
  float* wf = (float*)wsmA;
  for (int i = threadIdx.x; i < 18*CK; i += 256){
    int ch = i / CK, ct = i % CK;
    wf[ct*28 + ch] = offw[i];
  }
  for (int i = threadIdx.x; i < 9*CK; i += 256){
    int ch = i / CK, ct = i % CK;
    wf[ct*28 + 18 + ch] = modw[i];
  }
  for (int i = threadIdx.x; i < CK; i += 256) wf[i*28 + 27] = 0.f;
  __syncthreads();

  const int b  = blockIdx.y;
  const int wo = threadIdx.x & 127;
  const int ho = blockIdx.x*2 + (threadIdx.x >> 7);
  const float* xb = x + b*CN*HW;

  ull acc[14];
  #pragma unroll
  for (int j = 0; j < 14; j++) acc[j] = 0ull;

  const bool cok0 = (wo - 1) >= 0;
  const bool cok2 = (wo + 1) < WN;

  for (int c = 0; c < CN; ++c){
    const float* xc = xb + c*HW;
    float xv[3][3];
    #pragma unroll
    for (int r = 0; r < 3; r++){
      int row = ho - 1 + r;
      bool rok = (row >= 0) && (row < HN);
      const float* xr = xc + row*WN;
      xv[r][0] = (rok && cok0) ? xr[wo-1] : 0.f;
      xv[r][1] =  rok          ? xr[wo]   : 0.f;
      xv[r][2] = (rok && cok2) ? xr[wo+1] : 0.f;
    }
    #pragma unroll
    for (int ky = 0; ky < 3; ky++){
      #pragma unroll
      for (int kx = 0; kx < 3; kx++){
        const int tap = ky*3 + kx;
        ull a = pack2(xv[ky][kx], xv[ky][kx]);
        const ulonglong2* wp = (const ulonglong2*)(wsmA + (c*9 + tap)*14);
        #pragma unroll
        for (int j = 0; j < 7; j++){
          ulonglong2 w2 = wp[j];
          ffma2(acc[2*j],   w2.x, a);
          ffma2(acc[2*j+1], w2.y, a);
        }
      }
    }
  }

  float rr[28];
  #pragma unroll
  for (int j = 0; j < 14; j++) unpack2(acc[j], rr[2*j], rr[2*j+1]);
  write_pix(b, ho, wo, offb, modb, rr);
}

// ---------------- kernel B: weight convert to f16 [tap][o][c] ----------------
__global__ void prep_weights(const float* __restrict__ weight){
  int i = blockIdx.x*blockDim.x + threadIdx.x;
  if (i < K2C*ON*CN){
    int c = i & 63, o = (i >> 6) & 63, k = i >> 12;
    g_wh[i] = __float2half(weight[(o*CN + c)*K2C + k]);
  }
}

// ---------------- kernel C: bilinear sample + mma.sync HMMA ----------------
// CTA = one row: M=128 px, N=64 o. 256 threads = 8 warps, warp = m16 x n64.
// A: [128 px][72-pad halves] f16 (18432 B); W: [64 o][72-pad halves] f16 (9216 B).
// Pad 72 (144 B rows) => frag loads and staging hit distinct banks.
#define APAD 72

__global__ __launch_bounds__(256, 2)
void deform_mma(const float* __restrict__ x,
                const float* __restrict__ bias,
                float* __restrict__ out){
  __shared__ __half Asm[128*APAD];   // sampled tile
  __shared__ __half Wsm[ON*APAD];    // per-tap weight slice

  const int tid  = threadIdx.x;
  const int lane = tid & 31;
  const int wp   = tid >> 5;        // warp 0..7 -> px base wp*16
  const int g    = lane >> 2;       // groupID 0..7
  const int tg   = lane & 3;        // thread-in-group
  const int b    = blockIdx.y;
  const int ho   = blockIdx.x;
  const float* xb = x + b*CN*HW;

  // sampling mapping: px = tid&127, channels ch0..ch0+31
  const int px_s = tid & 127;
  const int ch0  = (tid >> 7) * 32;

  float acc[8][4];
  #pragma unroll
  for (int nt = 0; nt < 8; nt++)
    #pragma unroll
    for (int j = 0; j < 4; j++) acc[nt][j] = 0.f;

  for (int t = 0; t < 9; t++){
    if (t) __syncthreads();    // prior mma done reading Asm/Wsm

    // ---- stage W slice [64o][64c] f16 -> padded smem (8 x b32 per thread) ----
    {
      const uint32_t* src = (const uint32_t*)(g_wh + t*ON*CN);   // 2048 u32
      uint32_t* dst = (uint32_t*)Wsm;
      #pragma unroll
      for (int r = 0; r < 8; r++){
        int j = tid + r*256;
        int o = j >> 5, cp = j & 31;
        dst[o*(APAD/2) + cp] = src[j];
      }
    }

    // ---- bilinear sample 32 channels for my pixel -> A[px][c] f16 ----
    {
      const int sidx = ((b*9 + t)*HN + ho)*WN + px_s;
      float sy = g_sy[sidx], sx = g_sx[sidx];
      float y0f = floorf(sy), x0f = floorf(sx);
      float wy1 = sy - y0f, wx1 = sx - x0f;
      float wy0 = 1.f - wy1, wx0 = 1.f - wx1;
      int y0 = (int)y0f, x0i = (int)x0f;
      int y1 = y0 + 1,  x1i = x0i + 1;
      float my0 = (y0  >= 0 && y0  < HN) ? 1.f : 0.f;
      float my1 = (y1  >= 0 && y1  < HN) ? 1.f : 0.f;
      float mx0 = (x0i >= 0 && x0i < WN) ? 1.f : 0.f;
      float mx1 = (x1i >= 0 && x1i < WN) ? 1.f : 0.f;
      int cy0 = min(max(y0, 0), HN-1),  cy1 = min(max(y1, 0), HN-1);
      int cx0 = min(max(x0i, 0), WN-1), cx1 = min(max(x1i, 0), WN-1);
      int i00 = cy0*WN + cx0, i01 = cy0*WN + cx1;
      int i10 = cy1*WN + cx0, i11 = cy1*WN + cx1;
      float w00 = wy0*wx0*my0*mx0, w01 = wy0*wx1*my0*mx1;
      float w10 = wy1*wx0*my1*mx0, w11 = wy1*wx1*my1*mx1;
      const float* xc = xb + ch0*HW;
      #pragma unroll 4
      for (int i = 0; i < 32; i += 2){
        float v0 = w00*xc[i00] + w01*xc[i01] + w10*xc[i10] + w11*xc[i11];
        xc += HW;
        float v1 = w00*xc[i00] + w01*xc[i01] + w10*xc[i10] + w11*xc[i11];
        xc += HW;
        *(__half2*)&Asm[px_s*APAD + ch0 + i] = __floats2half2_rn(v0, v1);
      }
    }
    __syncthreads();

    // ---- HMMA: warp m16 x n64 x k64 ----
    const __half* Ar0 = Asm + (wp*16 + g)*APAD;
    const __half* Ar1 = Ar0 + 8*APAD;
    #pragma unroll
    for (int kt = 0; kt < 4; kt++){
      const int k0 = kt*16 + tg*2;
      uint32_t a0 = *(const uint32_t*)(Ar0 + k0);
      uint32_t a1 = *(const uint32_t*)(Ar1 + k0);
      uint32_t a2 = *(const uint32_t*)(Ar0 + k0 + 8);
      uint32_t a3 = *(const uint32_t*)(Ar1 + k0 + 8);
      #pragma unroll
      for (int nt = 0; nt < 8; nt++){
        const __half* Wr = Wsm + (nt*8 + g)*APAD + k0;
        uint32_t b0 = *(const uint32_t*)(Wr);
        uint32_t b1 = *(const uint32_t*)(Wr + 8);
        mma16816(acc[nt], a0, a1, a2, a3, b0, b1);
      }
    }
  }

  // ---- epilogue: * mod_mean + bias ----
  const int px0 = wp*16 + g;        // rows for c0,c1
  const int px1 = px0 + 8;          // rows for c2,c3
  const float mm0 = g_mm[(b*HN + ho)*WN + px0];
  const float mm1 = g_mm[(b*HN + ho)*WN + px1];
  #pragma unroll
  for (int nt = 0; nt < 8; nt++){
    int o0 = nt*8 + tg*2;
    float b0 = bias[o0], b1 = bias[o0 + 1];
    float* o0p = out + ((b*ON + o0    )*HN + ho)*WN;
    float* o1p = out + ((b*ON + o0 + 1)*HN + ho)*WN;
    o0p[px0] = acc[nt][0]*mm0 + b0;
    o1p[px0] = acc[nt][1]*mm0 + b1;
    o0p[px1] = acc[nt][2]*mm1 + b0;
    o1p[px1] = acc[nt][3]*mm1 + b1;
  }
}

// ---------------- launch ----------------
extern "C" void kernel_launch(void* const* d_in, const int* in_sizes, int n_in,
                              void* d_out, int out_size) {
  const float* x      = (const float*)d_in[0];
  const float* weight = (const float*)d_in[1];
  const float* bias   = (const float*)d_in[2];
  const float* offw   = (const float*)d_in[3];
  const float* offb   = (const float*)d_in[4];
  const float* modw   = (const float*)d_in[5];
  const float* modb   = (const float*)d_in[6];
  float* out = (float*)d_out;

  cudaFuncSetAttribute(offset_kernel, cudaFuncAttributeMaxDynamicSharedMemorySize, OSM_BYTES);

  offset_kernel<<<dim3(64, BN), 256, OSM_BYTES>>>(x, offw, modw, offb, modb);
  prep_weights<<<144, 256>>>(weight);
  deform_mma<<<dim3(HN, BN), 256>>>(x, bias, out);
}

// round 8
// speedup vs baseline: 2.1808x; 1.1608x over previous
#include <cuda_runtime.h>
#include <cuda_fp16.h>
#include <math.h>
#include <stdint.h>

// Problem constants
#define BN 4
#define CN 64
#define HN 128
#define WN 128
#define ON 64
#define K2C 9
#define HW (HN*WN)
#define CK 576          // CN * K2C

typedef unsigned long long ull;

// ---------------- scratch ----------------
__device__ __align__(16) float  g_sy[BN*K2C*HW];   // sample y coords
__device__ __align__(16) float  g_sx[BN*K2C*HW];   // sample x coords
__device__ __align__(16) float  g_mm[BN*HW];       // mean sigmoid modulation
__device__ __align__(16) __half g_wh[K2C*ON*CN];   // main weight f16 as [tap][o][c]

// ---------------- mma.sync m16n8k16 f16->f32 (base PTX, works on sm_103) ----------------
__device__ __forceinline__ void mma16816(float* d,
                                         uint32_t a0, uint32_t a1, uint32_t a2, uint32_t a3,
                                         uint32_t b0, uint32_t b1){
  asm volatile(
    "mma.sync.aligned.m16n8k16.row.col.f32.f16.f16.f32 "
    "{%0,%1,%2,%3}, {%4,%5,%6,%7}, {%8,%9}, {%0,%1,%2,%3};"
    : "+f"(d[0]), "+f"(d[1]), "+f"(d[2]), "+f"(d[3])
    : "r"(a0), "r"(a1), "r"(a2), "r"(a3), "r"(b0), "r"(b1));
}

// ---------------- kernel A: offset + modulation conv via HMMA ----------------
// CTA = one output row. 256 threads / 8 warps; warp = m16(px) x n32(ch) x k64(c) per tap.
// Xs: [3 rows][130 px (halo)][72-pad] f16; Ws: [9*32][72-pad] f16; Dsm aliases Xs.
#define XSP 72
#define XS_HALVES (3*130*XSP)            // 28080
#define WS_HALVES (K2C*32*XSP)           // 20736
#define OSM_BYTES ((XS_HALVES + WS_HALVES)*2)   // 97632 B

__device__ __forceinline__ void write_pix(int b, int ho, int wo,
                                          const float* __restrict__ offb,
                                          const float* __restrict__ modb,
                                          const float (&rr)[28]){
  float msum = 0.f;
  #pragma unroll
  for (int k = 0; k < 9; k++){
    float kyf = (float)(k/3) - 1.f;
    float kxf = (float)(k%3) - 1.f;
    int idx = ((b*9 + k)*HN + ho)*WN + wo;
    g_sy[idx] = (float)ho + kyf + rr[k]     + offb[k];
    g_sx[idx] = (float)wo + kxf + rr[9 + k] + offb[9 + k];
    float z = rr[18 + k] + modb[k];
    msum += 1.f / (1.f + expf(-z));
  }
  g_mm[(b*HN + ho)*WN + wo] = msum * (1.f/9.f);
}

__global__ __launch_bounds__(256, 2)
void offset_mma(const float* __restrict__ x,
                const float* __restrict__ offw,
                const float* __restrict__ modw,
                const float* __restrict__ offb,
                const float* __restrict__ modb){
  extern __shared__ char osm[];
  __half* Xs  = (__half*)osm;                    // [3][130][72]
  __half* Ws  = (__half*)osm + XS_HALVES;        // [288][72]
  float*  Dsm = (float*)osm;                     // [128][33] (aliases Xs after sync)

  const int tid  = threadIdx.x;
  const int lane = tid & 31;
  const int wp   = tid >> 5;
  const int g    = lane >> 2;
  const int tg   = lane & 3;
  const int b    = blockIdx.y;
  const int ho   = blockIdx.x;
  const float* xb = x + b*CN*HW;

  // ---- stage Xs: rows ho-1..ho+1, cols -1..128, zero-padded, f16 ----
  for (int j = tid; j < 3*130*64; j += 256){
    int c    = j / 390;
    int rem  = j % 390;
    int r    = rem / 130;
    int px_i = rem % 130;
    int row  = ho - 1 + r;
    int wo   = px_i - 1;
    float v = 0.f;
    if (row >= 0 && row < HN && wo >= 0 && wo < WN) v = xb[c*HW + row*WN + wo];
    Xs[(r*130 + px_i)*XSP + c] = __float2half(v);
  }

  // ---- stage Ws: [tap][32ch][64c] f16 (27 real channels + pad), from global ----
  for (int j = tid; j < K2C*32*32; j += 256){
    int tap = j / 1024;
    int rem = j % 1024;
    int ch  = rem / 32;
    int cp  = rem % 32;
    float v0 = 0.f, v1 = 0.f;
    int c0 = cp*2, c1 = cp*2 + 1;
    if (ch < 18){
      v0 = offw[ch*CK + c0*9 + tap];
      v1 = offw[ch*CK + c1*9 + tap];
    } else if (ch < 27){
      v0 = modw[(ch-18)*CK + c0*9 + tap];
      v1 = modw[(ch-18)*CK + c1*9 + tap];
    }
    ((uint32_t*)Ws)[(tap*32 + ch)*(XSP/2) + cp] = __half2_raw(__floats2half2_rn(v0, v1)).x
      | ((uint32_t)__half2_raw(__floats2half2_rn(v0, v1)).y << 16);
  }
  __syncthreads();

  // ---- HMMA: 9 taps x k64, warp m16 x n32 ----
  float acc[4][4];
  #pragma unroll
  for (int nt = 0; nt < 4; nt++)
    #pragma unroll
    for (int j = 0; j < 4; j++) acc[nt][j] = 0.f;

  #pragma unroll
  for (int t = 0; t < 9; t++){
    const int ky = t / 3, kx = t % 3;
    const __half* Ar0 = Xs + (ky*130 + wp*16 + g + kx)*XSP;
    const __half* Ar1 = Ar0 + 8*XSP;
    const __half* Wt  = Ws + (t*32)*XSP;
    #pragma unroll
    for (int kt = 0; kt < 4; kt++){
      const int k0 = kt*16 + tg*2;
      uint32_t a0 = *(const uint32_t*)(Ar0 + k0);
      uint32_t a1 = *(const uint32_t*)(Ar1 + k0);
      uint32_t a2 = *(const uint32_t*)(Ar0 + k0 + 8);
      uint32_t a3 = *(const uint32_t*)(Ar1 + k0 + 8);
      #pragma unroll
      for (int nt = 0; nt < 4; nt++){
        const __half* Wr = Wt + (nt*8 + g)*XSP + k0;
        uint32_t b0 = *(const uint32_t*)(Wr);
        uint32_t b1 = *(const uint32_t*)(Wr + 8);
        mma16816(acc[nt], a0, a1, a2, a3, b0, b1);
      }
    }
  }
  __syncthreads();   // done reading Xs; Dsm may overwrite

  // ---- scatter accumulators to Dsm[px][ch] (pad 33) ----
  {
    const int px0 = wp*16 + g;
    const int px1 = px0 + 8;
    #pragma unroll
    for (int nt = 0; nt < 4; nt++){
      int ch = nt*8 + tg*2;
      Dsm[px0*33 + ch]     = acc[nt][0];
      Dsm[px0*33 + ch + 1] = acc[nt][1];
      Dsm[px1*33 + ch]     = acc[nt][2];
      Dsm[px1*33 + ch + 1] = acc[nt][3];
    }
  }
  __syncthreads();

  // ---- per-pixel epilogue ----
  if (tid < 128){
    float rr[28];
    #pragma unroll
    for (int j = 0; j < 28; j++) rr[j] = Dsm[tid*33 + j];
    write_pix(b, ho, tid, offb, modb, rr);
  }
}

// ---------------- kernel B: weight convert to f16 [tap][o][c] ----------------
__global__ void prep_weights(const float* __restrict__ weight){
  int i = blockIdx.x*blockDim.x + threadIdx.x;
  if (i < K2C*ON*CN){
    int c = i & 63, o = (i >> 6) & 63, k = i >> 12;
    g_wh[i] = __float2half(weight[(o*CN + c)*K2C + k]);
  }
}

// ---------------- kernel C: bilinear sample + mma.sync HMMA (unchanged, R7) ----------------
#define APAD 72

__global__ __launch_bounds__(256, 2)
void deform_mma(const float* __restrict__ x,
                const float* __restrict__ bias,
                float* __restrict__ out){
  __shared__ __half Asm[128*APAD];   // sampled tile
  __shared__ __half Wsm[ON*APAD];    // per-tap weight slice

  const int tid  = threadIdx.x;
  const int lane = tid & 31;
  const int wp   = tid >> 5;
  const int g    = lane >> 2;
  const int tg   = lane & 3;
  const int b    = blockIdx.y;
  const int ho   = blockIdx.x;
  const float* xb = x + b*CN*HW;

  const int px_s = tid & 127;
  const int ch0  = (tid >> 7) * 32;

  float acc[8][4];
  #pragma unroll
  for (int nt = 0; nt < 8; nt++)
    #pragma unroll
    for (int j = 0; j < 4; j++) acc[nt][j] = 0.f;

  for (int t = 0; t < 9; t++){
    if (t) __syncthreads();

    // stage W slice [64o][64c] f16 -> padded smem
    {
      const uint32_t* src = (const uint32_t*)(g_wh + t*ON*CN);
      uint32_t* dst = (uint32_t*)Wsm;
      #pragma unroll
      for (int r = 0; r < 8; r++){
        int j = tid + r*256;
        int o = j >> 5, cp = j & 31;
        dst[o*(APAD/2) + cp] = src[j];
      }
    }

    // bilinear sample 32 channels for my pixel -> A[px][c] f16
    {
      const int sidx = ((b*9 + t)*HN + ho)*WN + px_s;
      float sy = g_sy[sidx], sx = g_sx[sidx];
      float y0f = floorf(sy), x0f = floorf(sx);
      float wy1 = sy - y0f, wx1 = sx - x0f;
      float wy0 = 1.f - wy1, wx0 = 1.f - wx1;
      int y0 = (int)y0f, x0i = (int)x0f;
      int y1 = y0 + 1,  x1i = x0i + 1;
      float my0 = (y0  >= 0 && y0  < HN) ? 1.f : 0.f;
      float my1 = (y1  >= 0 && y1  < HN) ? 1.f : 0.f;
      float mx0 = (x0i >= 0 && x0i < WN) ? 1.f : 0.f;
      float mx1 = (x1i >= 0 && x1i < WN) ? 1.f : 0.f;
      int cy0 = min(max(y0, 0), HN-1),  cy1 = min(max(y1, 0), HN-1);
      int cx0 = min(max(x0i, 0), WN-1), cx1 = min(max(x1i, 0), WN-1);
      int i00 = cy0*WN + cx0, i01 = cy0*WN + cx1;
      int i10 = cy1*WN + cx0, i11 = cy1*WN + cx1;
      float w00 = wy0*wx0*my0*mx0, w01 = wy0*wx1*my0*mx1;
      float w10 = wy1*wx0*my1*mx0, w11 = wy1*wx1*my1*mx1;
      const float* xc = xb + ch0*HW;
      #pragma unroll 4
      for (int i = 0; i < 32; i += 2){
        float v0 = w00*xc[i00] + w01*xc[i01] + w10*xc[i10] + w11*xc[i11];
        xc += HW;
        float v1 = w00*xc[i00] + w01*xc[i01] + w10*xc[i10] + w11*xc[i11];
        xc += HW;
        *(__half2*)&Asm[px_s*APAD + ch0 + i] = __floats2half2_rn(v0, v1);
      }
    }
    __syncthreads();

    // HMMA: warp m16 x n64 x k64
    const __half* Ar0 = Asm + (wp*16 + g)*APAD;
    const __half* Ar1 = Ar0 + 8*APAD;
    #pragma unroll
    for (int kt = 0; kt < 4; kt++){
      const int k0 = kt*16 + tg*2;
      uint32_t a0 = *(const uint32_t*)(Ar0 + k0);
      uint32_t a1 = *(const uint32_t*)(Ar1 + k0);
      uint32_t a2 = *(const uint32_t*)(Ar0 + k0 + 8);
      uint32_t a3 = *(const uint32_t*)(Ar1 + k0 + 8);
      #pragma unroll
      for (int nt = 0; nt < 8; nt++){
        const __half* Wr = Wsm + (nt*8 + g)*APAD + k0;
        uint32_t b0 = *(const uint32_t*)(Wr);
        uint32_t b1 = *(const uint32_t*)(Wr + 8);
        mma16816(acc[nt], a0, a1, a2, a3, b0, b1);
      }
    }
  }

  // epilogue: * mod_mean + bias
  const int px0 = wp*16 + g;
  const int px1 = px0 + 8;
  const float mm0 = g_mm[(b*HN + ho)*WN + px0];
  const float mm1 = g_mm[(b*HN + ho)*WN + px1];
  #pragma unroll
  for (int nt = 0; nt < 8; nt++){
    int o0 = nt*8 + tg*2;
    float b0 = bias[o0], b1 = bias[o0 + 1];
    float* o0p = out + ((b*ON + o0    )*HN + ho)*WN;
    float* o1p = out + ((b*ON + o0 + 1)*HN + ho)*WN;
    o0p[px0] = acc[nt][0]*mm0 + b0;
    o1p[px0] = acc[nt][1]*mm0 + b1;
    o0p[px1] = acc[nt][2]*mm1 + b0;
    o1p[px1] = acc[nt][3]*mm1 + b1;
  }
}

// ---------------- launch ----------------
extern "C" void kernel_launch(void* const* d_in, const int* in_sizes, int n_in,
                              void* d_out, int out_size) {
  const float* x      = (const float*)d_in[0];
  const float* weight = (const float*)d_in[1];
  const float* bias   = (const float*)d_in[2];
  const float* offw   = (const float*)d_in[3];
  const float* offb   = (const float*)d_in[4];
  const float* modw   = (const float*)d_in[5];
  const float* modb   = (const float*)d_in[6];
  float* out = (float*)d_out;

  cudaFuncSetAttribute(offset_mma, cudaFuncAttributeMaxDynamicSharedMemorySize, OSM_BYTES);

  offset_mma<<<dim3(HN, BN), 256, OSM_BYTES>>>(x, offw, modw, offb, modb);
  prep_weights<<<144, 256>>>(weight);
  deform_mma<<<dim3(HN, BN), 256>>>(x, bias, out);
}

// round 9
// speedup vs baseline: 2.7960x; 1.2821x over previous
#include <cuda_runtime.h>
#include <cuda_fp16.h>
#include <math.h>
#include <stdint.h>

// Problem constants
#define BN 4
#define CN 64
#define HN 128
#define WN 128
#define ON 64
#define K2C 9
#define HW (HN*WN)
#define CK 576          // CN * K2C

typedef unsigned long long ull;

// ---------------- scratch ----------------
__device__ __align__(16) float    g_sy[BN*K2C*HW];   // sample y coords
__device__ __align__(16) float    g_sx[BN*K2C*HW];   // sample x coords
__device__ __align__(16) float    g_mm[BN*HW];       // mean sigmoid modulation
__device__ __align__(16) __half   g_wh[K2C*ON*CN];   // main weight f16 [tap][o][c]
__device__ __align__(16) uint32_t g_wsA[K2C*32*36];  // offset+mod weight f16 pairs [tap][32ch][36]

// ---------------- mma.sync m16n8k16 f16->f32 (base PTX, works on sm_103) ----------------
__device__ __forceinline__ void mma16816(float* d,
                                         uint32_t a0, uint32_t a1, uint32_t a2, uint32_t a3,
                                         uint32_t b0, uint32_t b1){
  asm volatile(
    "mma.sync.aligned.m16n8k16.row.col.f32.f16.f16.f32 "
    "{%0,%1,%2,%3}, {%4,%5,%6,%7}, {%8,%9}, {%0,%1,%2,%3};"
    : "+f"(d[0]), "+f"(d[1]), "+f"(d[2]), "+f"(d[3])
    : "r"(a0), "r"(a1), "r"(a2), "r"(a3), "r"(b0), "r"(b1));
}

// ---------------- kernel B: one-time weight prep ----------------
// g_wh: main weight f16 [tap][o][c]; g_wsA: offset/mod weight padded f16 pairs.
__global__ void prep_weights(const float* __restrict__ weight,
                             const float* __restrict__ offw,
                             const float* __restrict__ modw){
  int i = blockIdx.x*blockDim.x + threadIdx.x;
  if (i < K2C*ON*CN){
    int c = i & 63, o = (i >> 6) & 63, k = i >> 12;
    g_wh[i] = __float2half(weight[(o*CN + c)*K2C + k]);
  }
  if (i < K2C*32*32){
    int tap = i >> 10;
    int rem = i & 1023;
    int ch  = rem >> 5;
    int cp  = rem & 31;
    float v0 = 0.f, v1 = 0.f;
    int c0 = cp*2, c1 = cp*2 + 1;
    if (ch < 18){
      v0 = offw[ch*CK + c0*9 + tap];
      v1 = offw[ch*CK + c1*9 + tap];
    } else if (ch < 27){
      v0 = modw[(ch-18)*CK + c0*9 + tap];
      v1 = modw[(ch-18)*CK + c1*9 + tap];
    }
    __half2 h2 = __floats2half2_rn(v0, v1);
    g_wsA[(tap*32 + ch)*36 + cp] = *(uint32_t*)&h2;
  }
  // zero the 4-u32 pad tail of each Ws row (keeps staging copy deterministic)
  if (i < K2C*32*4){
    int row = i >> 2, cp = 32 + (i & 3);
    g_wsA[row*36 + cp] = 0u;
  }
}

// ---------------- kernel A: offset + modulation conv via HMMA ----------------
#define XSP 72
#define XS_HALVES (3*130*XSP)            // 28080
#define WS_U32   (K2C*32*36)             // 10368
#define OSM_BYTES (XS_HALVES*2 + WS_U32*4)   // 97632 B

__device__ __forceinline__ void write_pix(int b, int ho, int wo,
                                          const float* __restrict__ offb,
                                          const float* __restrict__ modb,
                                          const float (&rr)[28]){
  float msum = 0.f;
  #pragma unroll
  for (int k = 0; k < 9; k++){
    float kyf = (float)(k/3) - 1.f;
    float kxf = (float)(k%3) - 1.f;
    int idx = ((b*9 + k)*HN + ho)*WN + wo;
    g_sy[idx] = (float)ho + kyf + rr[k]     + offb[k];
    g_sx[idx] = (float)wo + kxf + rr[9 + k] + offb[9 + k];
    float z = rr[18 + k] + modb[k];
    msum += 1.f / (1.f + expf(-z));
  }
  g_mm[(b*HN + ho)*WN + wo] = msum * (1.f/9.f);
}

__global__ __launch_bounds__(256, 2)
void offset_mma(const float* __restrict__ x,
                const float* __restrict__ offb,
                const float* __restrict__ modb){
  extern __shared__ char osm[];
  __half*   Xs  = (__half*)osm;                 // [3*130][72]
  uint32_t* Ws  = (uint32_t*)(osm + XS_HALVES*2); // [288][36]
  float*    Dsm = (float*)osm;                  // [128][33] (aliases Xs after sync)

  const int tid  = threadIdx.x;
  const int lane = tid & 31;
  const int wp   = tid >> 5;
  const int g    = lane >> 2;
  const int tg   = lane & 3;
  const int b    = blockIdx.y;
  const int ho   = blockIdx.x;
  const float* xb = x + b*CN*HW;

  // ---- stage Ws: straight float4 copy from precomputed global (no ALU) ----
  {
    const float4* src = (const float4*)g_wsA;    // 2592 float4
    float4* dst = (float4*)Ws;
    for (int i = tid; i < WS_U32/4; i += 256) dst[i] = src[i];
  }

  // ---- stage Xs: 2 positions/thread, div/mod hoisted, half2-packed STS ----
  #pragma unroll
  for (int pp = 0; pp < 2; pp++){
    int pos = tid + pp*256;
    if (pos < 390){
      int r    = pos / 130;
      int px_i = pos - r*130;
      int row  = ho - 1 + r;
      int wo   = px_i - 1;
      bool ok  = (row >= 0) && (row < HN) && (wo >= 0) && (wo < WN);
      const float* src = xb + row*WN + wo;
      uint32_t* dst = (uint32_t*)(Xs + pos*XSP);
      #pragma unroll 8
      for (int cp = 0; cp < 32; cp++){
        float v0 = ok ? src[(2*cp  )*HW] : 0.f;
        float v1 = ok ? src[(2*cp+1)*HW] : 0.f;
        __half2 h2 = __floats2half2_rn(v0, v1);
        dst[cp] = *(uint32_t*)&h2;
      }
    }
  }
  __syncthreads();

  // ---- HMMA: 9 taps x k64, warp m16 x n32 ----
  float acc[4][4];
  #pragma unroll
  for (int nt = 0; nt < 4; nt++)
    #pragma unroll
    for (int j = 0; j < 4; j++) acc[nt][j] = 0.f;

  #pragma unroll
  for (int t = 0; t < 9; t++){
    const int ky = t / 3, kx = t % 3;
    const __half* Ar0 = Xs + (ky*130 + wp*16 + g + kx)*XSP;
    const __half* Ar1 = Ar0 + 8*XSP;
    const uint32_t* Wt = Ws + (t*32)*36;
    #pragma unroll
    for (int kt = 0; kt < 4; kt++){
      const int k0 = kt*16 + tg*2;
      uint32_t a0 = *(const uint32_t*)(Ar0 + k0);
      uint32_t a1 = *(const uint32_t*)(Ar1 + k0);
      uint32_t a2 = *(const uint32_t*)(Ar0 + k0 + 8);
      uint32_t a3 = *(const uint32_t*)(Ar1 + k0 + 8);
      #pragma unroll
      for (int nt = 0; nt < 4; nt++){
        const uint32_t* Wr = Wt + (nt*8 + g)*36 + (k0 >> 1);
        uint32_t b0 = Wr[0];
        uint32_t b1 = Wr[4];
        mma16816(acc[nt], a0, a1, a2, a3, b0, b1);
      }
    }
  }
  __syncthreads();   // done reading Xs; Dsm may overwrite

  // ---- scatter accumulators to Dsm[px][ch] (pad 33) ----
  {
    const int px0 = wp*16 + g;
    const int px1 = px0 + 8;
    #pragma unroll
    for (int nt = 0; nt < 4; nt++){
      int ch = nt*8 + tg*2;
      Dsm[px0*33 + ch]     = acc[nt][0];
      Dsm[px0*33 + ch + 1] = acc[nt][1];
      Dsm[px1*33 + ch]     = acc[nt][2];
      Dsm[px1*33 + ch + 1] = acc[nt][3];
    }
  }
  __syncthreads();

  // ---- per-pixel epilogue ----
  if (tid < 128){
    float rr[28];
    #pragma unroll
    for (int j = 0; j < 28; j++) rr[j] = Dsm[tid*33 + j];
    write_pix(b, ho, tid, offb, modb, rr);
  }
}

// ---------------- kernel C: bilinear sample + mma.sync HMMA (unchanged, R7) ----------------
#define APAD 72

__global__ __launch_bounds__(256, 2)
void deform_mma(const float* __restrict__ x,
                const float* __restrict__ bias,
                float* __restrict__ out){
  __shared__ __half Asm[128*APAD];   // sampled tile
  __shared__ __half Wsm[ON*APAD];    // per-tap weight slice

  const int tid  = threadIdx.x;
  const int lane = tid & 31;
  const int wp   = tid >> 5;
  const int g    = lane >> 2;
  const int tg   = lane & 3;
  const int b    = blockIdx.y;
  const int ho   = blockIdx.x;
  const float* xb = x + b*CN*HW;

  const int px_s = tid & 127;
  const int ch0  = (tid >> 7) * 32;

  float acc[8][4];
  #pragma unroll
  for (int nt = 0; nt < 8; nt++)
    #pragma unroll
    for (int j = 0; j < 4; j++) acc[nt][j] = 0.f;

  for (int t = 0; t < 9; t++){
    if (t) __syncthreads();

    // stage W slice [64o][64c] f16 -> padded smem
    {
      const uint32_t* src = (const uint32_t*)(g_wh + t*ON*CN);
      uint32_t* dst = (uint32_t*)Wsm;
      #pragma unroll
      for (int r = 0; r < 8; r++){
        int j = tid + r*256;
        int o = j >> 5, cp = j & 31;
        dst[o*(APAD/2) + cp] = src[j];
      }
    }

    // bilinear sample 32 channels for my pixel -> A[px][c] f16
    {
      const int sidx = ((b*9 + t)*HN + ho)*WN + px_s;
      float sy = g_sy[sidx], sx = g_sx[sidx];
      float y0f = floorf(sy), x0f = floorf(sx);
      float wy1 = sy - y0f, wx1 = sx - x0f;
      float wy0 = 1.f - wy1, wx0 = 1.f - wx1;
      int y0 = (int)y0f, x0i = (int)x0f;
      int y1 = y0 + 1,  x1i = x0i + 1;
      float my0 = (y0  >= 0 && y0  < HN) ? 1.f : 0.f;
      float my1 = (y1  >= 0 && y1  < HN) ? 1.f : 0.f;
      float mx0 = (x0i >= 0 && x0i < WN) ? 1.f : 0.f;
      float mx1 = (x1i >= 0 && x1i < WN) ? 1.f : 0.f;
      int cy0 = min(max(y0, 0), HN-1),  cy1 = min(max(y1, 0), HN-1);
      int cx0 = min(max(x0i, 0), WN-1), cx1 = min(max(x1i, 0), WN-1);
      int i00 = cy0*WN + cx0, i01 = cy0*WN + cx1;
      int i10 = cy1*WN + cx0, i11 = cy1*WN + cx1;
      float w00 = wy0*wx0*my0*mx0, w01 = wy0*wx1*my0*mx1;
      float w10 = wy1*wx0*my1*mx0, w11 = wy1*wx1*my1*mx1;
      const float* xc = xb + ch0*HW;
      #pragma unroll 4
      for (int i = 0; i < 32; i += 2){
        float v0 = w00*xc[i00] + w01*xc[i01] + w10*xc[i10] + w11*xc[i11];
        xc += HW;
        float v1 = w00*xc[i00] + w01*xc[i01] + w10*xc[i10] + w11*xc[i11];
        xc += HW;
        *(__half2*)&Asm[px_s*APAD + ch0 + i] = __floats2half2_rn(v0, v1);
      }
    }
    __syncthreads();

    // HMMA: warp m16 x n64 x k64
    const __half* Ar0 = Asm + (wp*16 + g)*APAD;
    const __half* Ar1 = Ar0 + 8*APAD;
    #pragma unroll
    for (int kt = 0; kt < 4; kt++){
      const int k0 = kt*16 + tg*2;
      uint32_t a0 = *(const uint32_t*)(Ar0 + k0);
      uint32_t a1 = *(const uint32_t*)(Ar1 + k0);
      uint32_t a2 = *(const uint32_t*)(Ar0 + k0 + 8);
      uint32_t a3 = *(const uint32_t*)(Ar1 + k0 + 8);
      #pragma unroll
      for (int nt = 0; nt < 8; nt++){
        const __half* Wr = Wsm + (nt*8 + g)*APAD + k0;
        uint32_t b0 = *(const uint32_t*)(Wr);
        uint32_t b1 = *(const uint32_t*)(Wr + 8);
        mma16816(acc[nt], a0, a1, a2, a3, b0, b1);
      }
    }
  }

  // epilogue: * mod_mean + bias
  const int px0 = wp*16 + g;
  const int px1 = px0 + 8;
  const float mm0 = g_mm[(b*HN + ho)*WN + px0];
  const float mm1 = g_mm[(b*HN + ho)*WN + px1];
  #pragma unroll
  for (int nt = 0; nt < 8; nt++){
    int o0 = nt*8 + tg*2;
    float b0 = bias[o0], b1 = bias[o0 + 1];
    float* o0p = out + ((b*ON + o0    )*HN + ho)*WN;
    float* o1p = out + ((b*ON + o0 + 1)*HN + ho)*WN;
    o0p[px0] = acc[nt][0]*mm0 + b0;
    o1p[px0] = acc[nt][1]*mm0 + b1;
    o0p[px1] = acc[nt][2]*mm1 + b0;
    o1p[px1] = acc[nt][3]*mm1 + b1;
  }
}

// ---------------- launch ----------------
extern "C" void kernel_launch(void* const* d_in, const int* in_sizes, int n_in,
                              void* d_out, int out_size) {
  const float* x      = (const float*)d_in[0];
  const float* weight = (const float*)d_in[1];
  const float* bias   = (const float*)d_in[2];
  const float* offw   = (const float*)d_in[3];
  const float* offb   = (const float*)d_in[4];
  const float* modw   = (const float*)d_in[5];
  const float* modb   = (const float*)d_in[6];
  float* out = (float*)d_out;

  cudaFuncSetAttribute(offset_mma, cudaFuncAttributeMaxDynamicSharedMemorySize, OSM_BYTES);

  prep_weights<<<144, 256>>>(weight, offw, modw);
  offset_mma<<<dim3(HN, BN), 256, OSM_BYTES>>>(x, offb, modb);
  deform_mma<<<dim3(HN, BN), 256>>>(x, bias, out);
}

// round 11
// speedup vs baseline: 3.8473x; 1.3760x over previous
#include <cuda_runtime.h>
#include <cuda_fp16.h>
#include <math.h>
#include <stdint.h>

// Problem constants
#define BN 4
#define CN 64
#define HN 128
#define WN 128
#define ON 64
#define K2C 9
#define HW (HN*WN)
#define CK 576          // CN * K2C

typedef unsigned long long ull;

// ---------------- scratch ----------------
__device__ __align__(16) float    g_sy[BN*K2C*HW];   // sample y coords
__device__ __align__(16) float    g_sx[BN*K2C*HW];   // sample x coords
__device__ __align__(16) float    g_mm[BN*HW];       // mean sigmoid modulation
__device__ __align__(16) __half   g_wh[K2C*ON*CN];   // main weight f16 [tap][o][c]
__device__ __align__(16) uint32_t g_wsA[K2C*32*36];  // offset+mod weight f16 pairs [tap][32ch][36]
__device__ __align__(16) __half   g_xT[BN*HW*CN];    // x transposed, channel-last f16 [b][h*w][c]

// ---------------- mma.sync m16n8k16 f16->f32 (base PTX, works on sm_103) ----------------
__device__ __forceinline__ void mma16816(float* d,
                                         uint32_t a0, uint32_t a1, uint32_t a2, uint32_t a3,
                                         uint32_t b0, uint32_t b1){
  asm volatile(
    "mma.sync.aligned.m16n8k16.row.col.f32.f16.f16.f32 "
    "{%0,%1,%2,%3}, {%4,%5,%6,%7}, {%8,%9}, {%0,%1,%2,%3};"
    : "+f"(d[0]), "+f"(d[1]), "+f"(d[2]), "+f"(d[3])
    : "r"(a0), "r"(a1), "r"(a2), "r"(a3), "r"(b0), "r"(b1));
}

// ---------------- kernel T: transpose x -> channel-last f16 ----------------
__global__ __launch_bounds__(256)
void transpose_x(const float* __restrict__ x){
  __shared__ uint32_t T[128*36];   // [px][36 u32] = [px][72 halves], rows 144B
  const int b  = blockIdx.y;
  const int ho = blockIdx.x;
  const float* xr = x + b*CN*HW + ho*WN;

  // load + pack: thread j -> (cp = j>>7, px = j&127); coalesced along px
  for (int j = threadIdx.x; j < 32*128; j += 256){
    int cp = j >> 7, px = j & 127;
    float v0 = xr[(2*cp  )*HW + px];
    float v1 = xr[(2*cp+1)*HW + px];
    __half2 h2 = __floats2half2_rn(v0, v1);
    T[px*36 + cp] = *(uint32_t*)&h2;
  }
  __syncthreads();

  // store: 128 px x 8 x 16B chunks, coalesced STG.128
  float4* dst = (float4*)(g_xT + (b*HW + ho*WN)*CN);
  for (int j = threadIdx.x; j < 128*8; j += 256){
    int px = j >> 3, f4 = j & 7;
    dst[j] = *(float4*)&T[px*36 + f4*4];
  }
}

// ---------------- kernel B: one-time weight prep ----------------
__global__ void prep_weights(const float* __restrict__ weight,
                             const float* __restrict__ offw,
                             const float* __restrict__ modw){
  int i = blockIdx.x*blockDim.x + threadIdx.x;
  if (i < K2C*ON*CN){
    int c = i & 63, o = (i >> 6) & 63, k = i >> 12;
    g_wh[i] = __float2half(weight[(o*CN + c)*K2C + k]);
  }
  if (i < K2C*32*32){
    int tap = i >> 10;
    int rem = i & 1023;
    int ch  = rem >> 5;
    int cp  = rem & 31;
    float v0 = 0.f, v1 = 0.f;
    int c0 = cp*2, c1 = cp*2 + 1;
    if (ch < 18){
      v0 = offw[ch*CK + c0*9 + tap];
      v1 = offw[ch*CK + c1*9 + tap];
    } else if (ch < 27){
      v0 = modw[(ch-18)*CK + c0*9 + tap];
      v1 = modw[(ch-18)*CK + c1*9 + tap];
    }
    __half2 h2 = __floats2half2_rn(v0, v1);
    g_wsA[(tap*32 + ch)*36 + cp] = *(uint32_t*)&h2;
  }
  if (i < K2C*32*4){
    int row = i >> 2, cp = 32 + (i & 3);
    g_wsA[row*36 + cp] = 0u;
  }
}

// ---------------- kernel A: offset + modulation conv via HMMA ----------------
#define XSP 72
#define XS_HALVES (3*130*XSP)            // 28080
#define WS_U32   (K2C*32*36)             // 10368
#define OSM_BYTES (XS_HALVES*2 + WS_U32*4)   // 97632 B

__device__ __forceinline__ void write_pix(int b, int ho, int wo,
                                          const float* __restrict__ offb,
                                          const float* __restrict__ modb,
                                          const float (&rr)[28]){
  float msum = 0.f;
  #pragma unroll
  for (int k = 0; k < 9; k++){
    float kyf = (float)(k/3) - 1.f;
    float kxf = (float)(k%3) - 1.f;
    int idx = ((b*9 + k)*HN + ho)*WN + wo;
    g_sy[idx] = (float)ho + kyf + rr[k]     + offb[k];
    g_sx[idx] = (float)wo + kxf + rr[9 + k] + offb[9 + k];
    float z = rr[18 + k] + modb[k];
    msum += 1.f / (1.f + expf(-z));
  }
  g_mm[(b*HN + ho)*WN + wo] = msum * (1.f/9.f);
}

__global__ __launch_bounds__(256, 2)
void offset_mma(const float* __restrict__ offb,
                const float* __restrict__ modb){
  extern __shared__ char osm[];
  __half*   Xs  = (__half*)osm;                    // [3*130][72]
  uint32_t* Ws  = (uint32_t*)(osm + XS_HALVES*2);  // [288][36]
  float*    Dsm = (float*)osm;                     // [128][33] (aliases Xs after sync)

  const int tid  = threadIdx.x;
  const int lane = tid & 31;
  const int wp   = tid >> 5;
  const int g    = lane >> 2;
  const int tg   = lane & 3;
  const int b    = blockIdx.y;
  const int ho   = blockIdx.x;

  // ---- stage Ws: float4 copy from precomputed global ----
  {
    const float4* src = (const float4*)g_wsA;
    float4* dst = (float4*)Ws;
    for (int i = tid; i < WS_U32/4; i += 256) dst[i] = src[i];
  }

  // ---- stage Xs from channel-last g_xT: pure uint4 copy with zero halo ----
  {
    const int f4 = tid & 7;
    const uint4 zero4 = make_uint4(0,0,0,0);
    const __half* xtb = g_xT + b*HW*CN;
    for (int pos = tid >> 3; pos < 390; pos += 32){
      int r    = (pos >= 260) ? 2 : (pos >= 130 ? 1 : 0);
      int px_i = pos - r*130;
      int row  = ho - 1 + r;
      int wo   = px_i - 1;
      bool ok  = (row >= 0) && (row < HN) && (wo >= 0) && (wo < WN);
      uint4 v = ok ? *(const uint4*)(xtb + (row*WN + wo)*CN + f4*8) : zero4;
      *(uint4*)(Xs + pos*XSP + f4*8) = v;
    }
  }
  __syncthreads();

  // ---- HMMA: 9 taps x k64, warp m16 x n32 ----
  float acc[4][4];
  #pragma unroll
  for (int nt = 0; nt < 4; nt++)
    #pragma unroll
    for (int j = 0; j < 4; j++) acc[nt][j] = 0.f;

  #pragma unroll
  for (int t = 0; t < 9; t++){
    const int ky = t / 3, kx = t % 3;
    const __half* Ar0 = Xs + (ky*130 + wp*16 + g + kx)*XSP;
    const __half* Ar1 = Ar0 + 8*XSP;
    const uint32_t* Wt = Ws + (t*32)*36;
    #pragma unroll
    for (int kt = 0; kt < 4; kt++){
      const int k0 = kt*16 + tg*2;
      uint32_t a0 = *(const uint32_t*)(Ar0 + k0);
      uint32_t a1 = *(const uint32_t*)(Ar1 + k0);
      uint32_t a2 = *(const uint32_t*)(Ar0 + k0 + 8);
      uint32_t a3 = *(const uint32_t*)(Ar1 + k0 + 8);
      #pragma unroll
      for (int nt = 0; nt < 4; nt++){
        const uint32_t* Wr = Wt + (nt*8 + g)*36 + (k0 >> 1);
        uint32_t b0 = Wr[0];
        uint32_t b1 = Wr[4];
        mma16816(acc[nt], a0, a1, a2, a3, b0, b1);
      }
    }
  }
  __syncthreads();   // done reading Xs; Dsm may overwrite

  // ---- scatter accumulators to Dsm[px][ch] (pad 33) ----
  {
    const int px0 = wp*16 + g;
    const int px1 = px0 + 8;
    #pragma unroll
    for (int nt = 0; nt < 4; nt++){
      int ch = nt*8 + tg*2;
      Dsm[px0*33 + ch]     = acc[nt][0];
      Dsm[px0*33 + ch + 1] = acc[nt][1];
      Dsm[px1*33 + ch]     = acc[nt][2];
      Dsm[px1*33 + ch + 1] = acc[nt][3];
    }
  }
  __syncthreads();

  // ---- per-pixel epilogue ----
  if (tid < 128){
    float rr[28];
    #pragma unroll
    for (int j = 0; j < 28; j++) rr[j] = Dsm[tid*33 + j];
    write_pix(b, ho, tid, offb, modb, rr);
  }
}

// ---------------- kernel C: bilinear sample (channel-last, half2) + HMMA ----------------
#define APAD 72

__global__ __launch_bounds__(256, 2)
void deform_mma(const float* __restrict__ bias,
                float* __restrict__ out){
  __shared__ __half Asm[128*APAD];   // sampled tile
  __shared__ __half Wsm[ON*APAD];    // per-tap weight slice

  const int tid   = threadIdx.x;
  const int lane  = tid & 31;
  const int wp    = tid >> 5;
  const int g     = lane >> 2;
  const int tg    = lane & 3;
  const int pxo   = lane >> 3;      // 0..3 (sampling: px within quad)
  const int chunk = lane & 7;       // 0..7 (sampling: 8-channel chunk)
  const int b     = blockIdx.y;
  const int ho    = blockIdx.x;
  const __half* xtb = g_xT + b*HW*CN;

  float acc[8][4];
  #pragma unroll
  for (int nt = 0; nt < 8; nt++)
    #pragma unroll
    for (int j = 0; j < 4; j++) acc[nt][j] = 0.f;

  for (int t = 0; t < 9; t++){
    if (t) __syncthreads();

    // stage W slice [64o][64c] f16 -> padded smem
    {
      const uint32_t* src = (const uint32_t*)(g_wh + t*ON*CN);
      uint32_t* dst = (uint32_t*)Wsm;
      #pragma unroll
      for (int r = 0; r < 8; r++){
        int j = tid + r*256;
        int o = j >> 5, cp = j & 31;
        dst[o*(APAD/2) + cp] = src[j];
      }
    }

    // ---- sampling: warp covers 16 px; lane = (pxo, chunk); full-line LDG.128 gathers ----
    #pragma unroll
    for (int it = 0; it < 4; it++){
      const int px = wp*16 + it*4 + pxo;
      const int sidx = ((b*9 + t)*HN + ho)*WN + px;
      float sy = g_sy[sidx], sx = g_sx[sidx];
      float y0f = floorf(sy), x0f = floorf(sx);
      float wy1 = sy - y0f, wx1 = sx - x0f;
      float wy0 = 1.f - wy1, wx0 = 1.f - wx1;
      int y0 = (int)y0f, x0i = (int)x0f;
      int y1 = y0 + 1,  x1i = x0i + 1;
      float my0 = (y0  >= 0 && y0  < HN) ? 1.f : 0.f;
      float my1 = (y1  >= 0 && y1  < HN) ? 1.f : 0.f;
      float mx0 = (x0i >= 0 && x0i < WN) ? 1.f : 0.f;
      float mx1 = (x1i >= 0 && x1i < WN) ? 1.f : 0.f;
      int cy0 = min(max(y0, 0), HN-1),  cy1 = min(max(y1, 0), HN-1);
      int cx0 = min(max(x0i, 0), WN-1), cx1 = min(max(x1i, 0), WN-1);
      __half2 W00 = __float2half2_rn(wy0*wx0*my0*mx0);
      __half2 W01 = __float2half2_rn(wy0*wx1*my0*mx1);
      __half2 W10 = __float2half2_rn(wy1*wx0*my1*mx0);
      __half2 W11 = __float2half2_rn(wy1*wx1*my1*mx1);

      const int co = chunk*8;
      uint4 c00 = *(const uint4*)(xtb + (cy0*WN + cx0)*CN + co);
      uint4 c01 = *(const uint4*)(xtb + (cy0*WN + cx1)*CN + co);
      uint4 c10 = *(const uint4*)(xtb + (cy1*WN + cx0)*CN + co);
      uint4 c11 = *(const uint4*)(xtb + (cy1*WN + cx1)*CN + co);

      __half2 s[4];
      const __half2* h00 = (const __half2*)&c00;
      const __half2* h01 = (const __half2*)&c01;
      const __half2* h10 = (const __half2*)&c10;
      const __half2* h11 = (const __half2*)&c11;
      #pragma unroll
      for (int j = 0; j < 4; j++){
        __half2 a = __hmul2(W00, h00[j]);
        a = __hfma2(W01, h01[j], a);
        a = __hfma2(W10, h10[j], a);
        a = __hfma2(W11, h11[j], a);
        s[j] = a;
      }
      *(uint4*)&Asm[px*APAD + co] = *(uint4*)s;
    }
    __syncthreads();

    // HMMA: warp m16 x n64 x k64
    const __half* Ar0 = Asm + (wp*16 + g)*APAD;
    const __half* Ar1 = Ar0 + 8*APAD;
    #pragma unroll
    for (int kt = 0; kt < 4; kt++){
      const int k0 = kt*16 + tg*2;
      uint32_t a0 = *(const uint32_t*)(Ar0 + k0);
      uint32_t a1 = *(const uint32_t*)(Ar1 + k0);
      uint32_t a2 = *(const uint32_t*)(Ar0 + k0 + 8);
      uint32_t a3 = *(const uint32_t*)(Ar1 + k0 + 8);
      #pragma unroll
      for (int nt = 0; nt < 8; nt++){
        const __half* Wr = Wsm + (nt*8 + g)*APAD + k0;
        uint32_t b0 = *(const uint32_t*)(Wr);
        uint32_t b1 = *(const uint32_t*)(Wr + 8);
        mma16816(acc[nt], a0, a1, a2, a3, b0, b1);
      }
    }
  }

  // epilogue: * mod_mean + bias
  const int px0 = wp*16 + g;
  const int px1 = px0 + 8;
  const float mm0 = g_mm[(b*HN + ho)*WN + px0];
  const float mm1 = g_mm[(b*HN + ho)*WN + px1];
  #pragma unroll
  for (int nt = 0; nt < 8; nt++){
    int o0 = nt*8 + tg*2;
    float b0 = bias[o0], b1 = bias[o0 + 1];
    float* o0p = out + ((b*ON + o0    )*HN + ho)*WN;
    float* o1p = out + ((b*ON + o0 + 1)*HN + ho)*WN;
    o0p[px0] = acc[nt][0]*mm0 + b0;
    o1p[px0] = acc[nt][1]*mm0 + b1;
    o0p[px1] = acc[nt][2]*mm1 + b0;
    o1p[px1] = acc[nt][3]*mm1 + b1;
  }
}

// ---------------- launch ----------------
extern "C" void kernel_launch(void* const* d_in, const int* in_sizes, int n_in,
                              void* d_out, int out_size) {
  const float* x      = (const float*)d_in[0];
  const float* weight = (const float*)d_in[1];
  const float* bias   = (const float*)d_in[2];
  const float* offw   = (const float*)d_in[3];
  const float* offb   = (const float*)d_in[4];
  const float* modw   = (const float*)d_in[5];
  const float* modb   = (const float*)d_in[6];
  float* out = (float*)d_out;

  cudaFuncSetAttribute(offset_mma, cudaFuncAttributeMaxDynamicSharedMemorySize, OSM_BYTES);

  transpose_x<<<dim3(HN, BN), 256>>>(x);
  prep_weights<<<144, 256>>>(weight, offw, modw);
  offset_mma<<<dim3(HN, BN), 256, OSM_BYTES>>>(offb, modb);
  deform_mma<<<dim3(HN, BN), 256>>>(bias, out);
}